// round 9
// baseline (speedup 1.0000x reference)
#include <cuda_runtime.h>
#include <cuda_bf16.h>

// Problem constants (match reference)
#define SIZE     16384      // 128*128 points per batch
#define KNN      16
#define ND       5          // num derivatives (order 2, 2D)
#define NBATCH   32
#define CHUNKS   4          // CTAs per batch -> grid 128 (single wave)
#define CTA_PTS  (SIZE / CHUNKS)   // 4096 points per CTA
#define NTHREADS 1024
#define PTS_PER_THREAD (CTA_PTS / NTHREADS)  // 4

// Dynamic smem: float2 pxy[SIZE] (128KB) + float sv[SIZE] (64KB)
#define SMEM_BYTES (SIZE * sizeof(float2) + SIZE * sizeof(float))  // 196608

__device__ __forceinline__ float frcp_fast(float x) {
    float r; asm("rcp.approx.f32 %0, %1;" : "=f"(r) : "f"(x)); return r;
}

// ---------------------------------------------------------------------------
// Per-point: accumulate the 12 distinct Gram monomials w^2 dx^p dy^q
// (p+q in [2,4]) + 5 rhs terms, then solve the 5x5 SPD system.
// Columns scaled by D = diag(1,1,2,1,2) vs the reference Taylor design;
// exact equivalence restored by ridge {1,1,4,1,4}*1e-6 and folded weights.
// Pivot reciprocals are computed once and reused in back-substitution.
// ---------------------------------------------------------------------------
__device__ __forceinline__ float point_du(
    const float2* __restrict__ pxy, const float* __restrict__ sv,
    const int* __restrict__ eidx_g, const float* __restrict__ dist_g,
    const float* __restrict__ wf,   // folded weights {w0,w1,2w2,w3,2w4}
    int s, float2 pc, float vc)
{
    const int4*   ei4 = reinterpret_cast<const int4*>(eidx_g + (size_t)s * KNN);
    const float4* dw4 = reinterpret_cast<const float4*>(dist_g + (size_t)s * KNN);

    float M20=0,M11=0,M02=0;                 // degree-2 monomials
    float M30=0,M21=0,M12=0,M03=0;           // degree-3
    float M40=0,M31=0,M22=0,M13=0,M04=0;     // degree-4
    float b0=0,b1=0,b2=0,b3=0,b4=0;          // rhs

    #pragma unroll
    for (int g = 0; g < 4; ++g) {
        const int4   ei = ei4[g];
        const float4 dw = dw4[g];
        const int   idx[4] = {ei.x, ei.y, ei.z, ei.w};
        const float wts[4] = {dw.x, dw.y, dw.z, dw.w};

        #pragma unroll
        for (int j = 0; j < 4; ++j) {
            const int    id = idx[j];
            const float  w  = wts[j];
            const float2 pn = pxy[id];     // LDS.64
            const float  vn = sv[id];      // LDS.32

            const float dx = pn.x - pc.x;
            const float dy = pn.y - pc.y;
            const float p0 = dx * w;       // w dx
            const float p1 = dy * w;       // w dy
            const float q0 = p0 * dx;      // w dx^2
            const float q1 = p0 * dy;      // w dx dy
            const float q2 = p1 * dy;      // w dy^2
            const float r  = (vn - vc) * w;

            M20 = fmaf(p0, p0, M20); M11 = fmaf(p0, p1, M11); M02 = fmaf(p1, p1, M02);
            M30 = fmaf(q0, p0, M30); M21 = fmaf(q0, p1, M21);
            M12 = fmaf(q1, p1, M12); M03 = fmaf(q2, p1, M03);
            M40 = fmaf(q0, q0, M40); M31 = fmaf(q0, q1, M31); M22 = fmaf(q0, q2, M22);
            M13 = fmaf(q1, q2, M13); M04 = fmaf(q2, q2, M04);
            b0 = fmaf(p0, r, b0); b1 = fmaf(p1, r, b1);
            b2 = fmaf(q0, r, b2); b3 = fmaf(q1, r, b3); b4 = fmaf(q2, r, b4);
        }
    }

    // Expand monomials into the upper-triangular Gram matrix + scaled ridge.
    float m[ND][ND];
    m[0][0]=M20+1e-6f; m[0][1]=M11; m[0][2]=M30; m[0][3]=M21; m[0][4]=M12;
    m[1][1]=M02+1e-6f; m[1][2]=M21; m[1][3]=M12; m[1][4]=M03;
    m[2][2]=M40+4e-6f; m[2][3]=M31; m[2][4]=M22;
    m[3][3]=M22+1e-6f; m[3][4]=M13;
    m[4][4]=M04+4e-6f;
    float bv[ND] = {b0, b1, b2, b3, b4};

    // symmetric unpivoted Gaussian elimination; cache pivot reciprocals
    float invd[ND];
    #pragma unroll
    for (int i = 0; i < ND; ++i) {
        invd[i] = frcp_fast(m[i][i]);
        #pragma unroll
        for (int r2 = i + 1; r2 < ND; ++r2) {
            const float f = m[i][r2] * invd[i];
            #pragma unroll
            for (int c = r2; c < ND; ++c) m[r2][c] = fmaf(-f, m[i][c], m[r2][c]);
            bv[r2] = fmaf(-f, bv[i], bv[r2]);
        }
    }
    // back substitution using cached reciprocals; accumulate du
    float sol[ND];
    float du = 0.f;
    #pragma unroll
    for (int i = ND - 1; i >= 0; --i) {
        float acc = bv[i];
        #pragma unroll
        for (int c = i + 1; c < ND; ++c) acc = fmaf(-m[i][c], sol[c], acc);
        sol[i] = acc * invd[i];
        du = fmaf(sol[i], wf[i], du);
    }
    return du;
}

// ---------------------------------------------------------------------------
// Primary kernel: grid 128 (single wave), full batch in 192 KB smem, one
// staging per CTA. Point loop fully unrolled so ptxas can overlap the solve
// of point p with the gathers of point p+1.
// ---------------------------------------------------------------------------
__global__ void __launch_bounds__(NTHREADS, 1)
tp_layer_smem_kernel(const float* __restrict__ x,
                     const float* __restrict__ points,
                     const int*   __restrict__ edge_index,
                     const float* __restrict__ dt_p,
                     const float* __restrict__ dist,
                     const float* __restrict__ weight,
                     float* __restrict__ out)
{
    extern __shared__ float smem[];
    float2* pxy = reinterpret_cast<float2*>(smem);   // [SIZE]
    float*  sv  = smem + 2 * SIZE;                    // [SIZE]

    const int b     = blockIdx.x / CHUNKS;
    const int chunk = blockIdx.x % CHUNKS;
    const int tid   = threadIdx.x;

    const float* pts_b = points + (size_t)b * SIZE * 2;
    const float* x_b   = x + (size_t)b * SIZE;

    // Stage batch into smem: coalesced float4 copies (layout identical).
    {
        float4* dstp = reinterpret_cast<float4*>(pxy);
        const float4* srcp = reinterpret_cast<const float4*>(pts_b);
        #pragma unroll
        for (int i = 0; i < (SIZE * 2 / 4) / NTHREADS; ++i)   // 8 iters
            dstp[tid + i * NTHREADS] = srcp[tid + i * NTHREADS];

        float4* dstx = reinterpret_cast<float4*>(sv);
        const float4* srcx = reinterpret_cast<const float4*>(x_b);
        #pragma unroll
        for (int i = 0; i < (SIZE / 4) / NTHREADS; ++i)       // 4 iters
            dstx[tid + i * NTHREADS] = srcx[tid + i * NTHREADS];
    }
    __syncthreads();

    const float dt = dt_p[0];
    float wf[ND];
    wf[0] = weight[0]; wf[1] = weight[1]; wf[2] = 2.f * weight[2];
    wf[3] = weight[3]; wf[4] = 2.f * weight[4];

    const int s_base = chunk * CTA_PTS;
    const int*   eidx_g = edge_index + (size_t)b * SIZE * KNN;
    const float* dist_g = dist       + (size_t)b * SIZE * KNN;

    #pragma unroll
    for (int p = 0; p < PTS_PER_THREAD; ++p) {
        const int s = s_base + tid + p * NTHREADS;
        const float2 pc = pxy[s];
        const float  vc = sv[s];
        const float du = point_du(pxy, sv, eidx_g, dist_g, wf, s, pc, vc);
        out[(size_t)b * SIZE + s] = vc + dt * du;
    }
}

// ---------------------------------------------------------------------------
// Fallback kernel (global-memory gathers, no opt-in smem) — env insurance only
// ---------------------------------------------------------------------------
__global__ void __launch_bounds__(256)
tp_layer_fallback_kernel(const float* __restrict__ x,
                         const float* __restrict__ points,
                         const int*   __restrict__ edge_index,
                         const float* __restrict__ dt_p,
                         const float* __restrict__ dist,
                         const float* __restrict__ weight,
                         float* __restrict__ out,
                         int total)
{
    int gid = blockIdx.x * blockDim.x + threadIdx.x;
    if (gid >= total) return;
    const int b = gid >> 14;
    const int s = gid & (SIZE - 1);

    const float* pts_b = points + (size_t)b * SIZE * 2;
    const float* x_b   = x + (size_t)b * SIZE;
    const float2 pc = *reinterpret_cast<const float2*>(pts_b + 2 * s);
    const float  vc = x_b[s];

    const int4*   ei4 = reinterpret_cast<const int4*>(edge_index + (size_t)b * SIZE * KNN + (size_t)s * KNN);
    const float4* dw4 = reinterpret_cast<const float4*>(dist       + (size_t)b * SIZE * KNN + (size_t)s * KNN);

    float M20=0,M11=0,M02=0,M30=0,M21=0,M12=0,M03=0,M40=0,M31=0,M22=0,M13=0,M04=0;
    float b0=0,b1=0,b2=0,b3=0,b4=0;
    #pragma unroll
    for (int g = 0; g < 4; ++g) {
        const int4   ei = ei4[g];
        const float4 dw = dw4[g];
        const int   idx[4] = {ei.x, ei.y, ei.z, ei.w};
        const float wts[4] = {dw.x, dw.y, dw.z, dw.w};
        #pragma unroll
        for (int j = 0; j < 4; ++j) {
            const int id = idx[j];
            const float2 pn = *reinterpret_cast<const float2*>(pts_b + 2 * id);
            const float dx = pn.x - pc.x, dy = pn.y - pc.y;
            const float w = wts[j];
            const float p0 = dx*w, p1 = dy*w;
            const float q0 = p0*dx, q1 = p0*dy, q2 = p1*dy;
            const float r = (x_b[id] - vc) * w;
            M20 = fmaf(p0,p0,M20); M11 = fmaf(p0,p1,M11); M02 = fmaf(p1,p1,M02);
            M30 = fmaf(q0,p0,M30); M21 = fmaf(q0,p1,M21);
            M12 = fmaf(q1,p1,M12); M03 = fmaf(q2,p1,M03);
            M40 = fmaf(q0,q0,M40); M31 = fmaf(q0,q1,M31); M22 = fmaf(q0,q2,M22);
            M13 = fmaf(q1,q2,M13); M04 = fmaf(q2,q2,M04);
            b0 = fmaf(p0,r,b0); b1 = fmaf(p1,r,b1);
            b2 = fmaf(q0,r,b2); b3 = fmaf(q1,r,b3); b4 = fmaf(q2,r,b4);
        }
    }
    float m[ND][ND];
    m[0][0]=M20+1e-6f; m[0][1]=M11; m[0][2]=M30; m[0][3]=M21; m[0][4]=M12;
    m[1][1]=M02+1e-6f; m[1][2]=M21; m[1][3]=M12; m[1][4]=M03;
    m[2][2]=M40+4e-6f; m[2][3]=M31; m[2][4]=M22;
    m[3][3]=M22+1e-6f; m[3][4]=M13;
    m[4][4]=M04+4e-6f;
    float bv[ND] = {b0, b1, b2, b3, b4};
    float invd[ND];
    #pragma unroll
    for (int i = 0; i < ND; ++i) {
        invd[i] = frcp_fast(m[i][i]);
        #pragma unroll
        for (int r2 = i + 1; r2 < ND; ++r2) {
            const float f = m[i][r2] * invd[i];
            #pragma unroll
            for (int c = r2; c < ND; ++c) m[r2][c] = fmaf(-f, m[i][c], m[r2][c]);
            bv[r2] = fmaf(-f, bv[i], bv[r2]);
        }
    }
    float sol[ND];
    float du = 0.f;
    const float wf[ND] = {weight[0], weight[1], 2.f*weight[2], weight[3], 2.f*weight[4]};
    #pragma unroll
    for (int i = ND - 1; i >= 0; --i) {
        float acc = bv[i];
        #pragma unroll
        for (int c = i + 1; c < ND; ++c) acc = fmaf(-m[i][c], sol[c], acc);
        sol[i] = acc * invd[i];
        du = fmaf(sol[i], wf[i], du);
    }
    out[gid] = vc + dt_p[0] * du;
}

extern "C" void kernel_launch(void* const* d_in, const int* in_sizes, int n_in,
                              void* d_out, int out_size)
{
    const float* x      = (const float*)d_in[0];
    const float* points = (const float*)d_in[1];
    const int*   eidx   = (const int*)  d_in[2];
    const float* dt     = (const float*)d_in[3];
    const float* dist   = (const float*)d_in[4];
    const float* weight = (const float*)d_in[5];
    float* out = (float*)d_out;

    // Opt-in smem; environment-deterministic, identical on every call.
    cudaError_t attr_ok = cudaFuncSetAttribute(
        tp_layer_smem_kernel,
        cudaFuncAttributeMaxDynamicSharedMemorySize,
        SMEM_BYTES);

    if (attr_ok == cudaSuccess) {
        tp_layer_smem_kernel<<<NBATCH * CHUNKS, NTHREADS, SMEM_BYTES>>>(
            x, points, eidx, dt, dist, weight, out);
    } else {
        const int total = out_size;
        tp_layer_fallback_kernel<<<(total + 255) / 256, 256>>>(
            x, points, eidx, dt, dist, weight, out, total);
    }
}